// round 6
// baseline (speedup 1.0000x reference)
#include <cuda_runtime.h>
#include <math.h>

#define B_    32
#define INC_  10
#define LIN_  16384
#define CH_   20
#define NPOLY 12
#define MM_   6
#define NB_   4
// lengths: l0=16434 -> 16422,16410,16398,16386 (all divisible by 6)

#define BUFN 10520000  // >= 32*20*16434

__device__ float g_xa[BUFN];
__device__ float g_xb[BUFN];
__device__ float g_y1[BUFN];
__device__ float g_y2[BUFN];

// All small weights live in constant memory (warp-uniform -> LDCU port,
// keeps the LDS crossbar free for activations).
__constant__ float c_wfirst[CH_ * INC_ * 3];        // 600
__constant__ float c_conva[NB_ * CH_ * CH_ * 3];    // 4800
__constant__ float c_convb[NB_ * CH_ * CH_ * 3];    // 4800
__constant__ float c_linm[NB_ * CH_ * MM_ * MM_];   // 2880
__constant__ float c_fd[MM_ * NPOLY];               // 72
__constant__ float c_fr[MM_ * NPOLY];               // 72

typedef unsigned long long ull;

__device__ __forceinline__ ull pk2(float lo, float hi) {
    ull r; asm("mov.b64 %0, {%1, %2};" : "=l"(r) : "f"(lo), "f"(hi)); return r;
}
__device__ __forceinline__ void upk2(ull v, float& lo, float& hi) {
    asm("mov.b64 {%0, %1}, %2;" : "=f"(lo), "=f"(hi) : "l"(v));
}
__device__ __forceinline__ ull fma2(ull a, ull b, ull c) {
    ull d; asm("fma.rn.f32x2 %0, %1, %2, %3;" : "=l"(d) : "l"(a), "l"(b), "l"(c));
    return d;
}

// Branchless gelu: Abramowitz-Stegun 7.1.26 erf approx (|abs err| < 1.5e-7)
__device__ __forceinline__ float gelu_f(float x) {
    float z = 0.7071067811865476f * x;
    float s = fabsf(z);
    float t = __fdividef(1.0f, fmaf(0.3275911f, s, 1.0f));
    float p = fmaf(fmaf(fmaf(fmaf(1.061405429f, t, -1.453152027f),
                             t, 1.421413741f), t, -0.284496736f), t, 0.254829592f) * t;
    float e = __expf(-s * s);
    float er = fmaf(-p, e, 1.0f);
    er = copysignf(er, z);
    return 0.5f * x * (1.0f + er);
}

// ---------------------------------------------------------------------------
// First conv: input (B,10,16384) wrap-padded (25,27), conv3 -> (B,20,16434)
// Weights from constant memory.
// ---------------------------------------------------------------------------
__global__ void __launch_bounds__(128) k_first(
    const float* __restrict__ in, float* __restrict__ out, int lout)
{
    int b = blockIdx.y;
    int t = blockIdx.x * blockDim.x + threadIdx.x;
    if (t >= lout) return;

    int base = t - 25;
    int i0 = base;     if (i0 < 0) i0 += LIN_; else if (i0 >= LIN_) i0 -= LIN_;
    int i1 = base + 1; if (i1 < 0) i1 += LIN_; else if (i1 >= LIN_) i1 -= LIN_;
    int i2 = base + 2; if (i2 < 0) i2 += LIN_; else if (i2 >= LIN_) i2 -= LIN_;

    const float* inb = in + (size_t)b * INC_ * LIN_;
    float acc[CH_];
#pragma unroll
    for (int co = 0; co < CH_; co++) acc[co] = 0.f;
#pragma unroll
    for (int ci = 0; ci < INC_; ci++) {
        float v0 = inb[ci * LIN_ + i0];
        float v1 = inb[ci * LIN_ + i1];
        float v2 = inb[ci * LIN_ + i2];
#pragma unroll
        for (int co = 0; co < CH_; co++) {
            int wi = (co * INC_ + ci) * 3;
            acc[co] = fmaf(c_wfirst[wi], v0,
                      fmaf(c_wfirst[wi + 1], v1,
                      fmaf(c_wfirst[wi + 2], v2, acc[co])));
        }
    }
    float* ob = out + (size_t)b * CH_ * lout;
#pragma unroll
    for (int co = 0; co < CH_; co++) ob[co * lout + t] = acc[co];
}

// ---------------------------------------------------------------------------
// conv3 20->20 VALID, weights in constant (IS_A selects bank), optional gelu.
// 4 warps x 5 co each; V=6 positions/thread; tile NTC=192.
// ---------------------------------------------------------------------------
#define NTC 192
#define XROW 200

template <bool DO_GELU, bool IS_A>
__global__ void __launch_bounds__(128) k_conv5c(
    const float* __restrict__ x, float* __restrict__ out, int lin, int wofs)
{
    __shared__ float xs[CH_][XROW];

    int tid = threadIdx.x;
    int b = blockIdx.y;
    int T0 = blockIdx.x * NTC;
    int lout = lin - 2;

    for (int i = tid; i < CH_ * (NTC + 2); i += 128) {
        int ci = i / (NTC + 2), j = i % (NTC + 2);
        int gp = T0 + j;
        xs[ci][j] = (gp < lin) ? x[((size_t)b * CH_ + ci) * lin + gp] : 0.f;
    }
    __syncthreads();

    int wq = tid >> 5, lane = tid & 31;
    int cob = 5 * wq;

    float a[5][6];
#pragma unroll
    for (int cc = 0; cc < 5; cc++)
#pragma unroll
        for (int v = 0; v < 6; v++) a[cc][v] = 0.f;

#pragma unroll
    for (int ci = 0; ci < CH_; ci++) {
        float wr[15];
#pragma unroll
        for (int cc = 0; cc < 5; cc++)
#pragma unroll
            for (int k = 0; k < 3; k++) {
                int wi = wofs + ((cob + cc) * CH_ + ci) * 3 + k;
                wr[cc * 3 + k] = IS_A ? c_conva[wi] : c_convb[wi];
            }
#pragma unroll
        for (int v = 0; v < 6; v++) {
            int j = lane + 32 * v;
            float x0 = xs[ci][j], x1 = xs[ci][j + 1], x2 = xs[ci][j + 2];
#pragma unroll
            for (int cc = 0; cc < 5; cc++)
                a[cc][v] = fmaf(wr[cc * 3], x0,
                           fmaf(wr[cc * 3 + 1], x1,
                           fmaf(wr[cc * 3 + 2], x2, a[cc][v])));
        }
    }
#pragma unroll
    for (int v = 0; v < 6; v++) {
        int t = T0 + lane + 32 * v;
        if (t < lout) {
#pragma unroll
            for (int cc = 0; cc < 5; cc++) {
                float u = a[cc][v];
                if (DO_GELU) u = gelu_f(u);
                out[((size_t)b * CH_ + cob + cc) * lout + t] = u;
            }
        }
    }
}

// ---------------------------------------------------------------------------
// Legendre decomposition + cross-channel block-diag mixing, conflict-free.
// Staged layout: xs6p[ci][r][tau] = {x[6tau+r], x[6tau+r+6]} (float2),
// so compute reads are stride-1 LDS.64. Weights fd/lm from constant
// (warp-uniform: threadIdx.y = g constant within a warp).
// NOTE: 0.5 quadrature factor deferred to k_recon.
//   v[q,tau] = sum_r fd[mi,r]*P.x + fd[mi,r+6]*P.y, q=6g+i, mi=q/20, ci=q%20
//   u[p,tau] = sum_i lm[g,p%6,i]*v[i]
// Lg layout [b][mo][co][ll], p = mo*20+co.
// ---------------------------------------------------------------------------
#define TB_ 32
__global__ void __launch_bounds__(640) k_legmix(
    const float* __restrict__ x, float* __restrict__ Lg,
    int lin, int ll, int lmofs)
{
    __shared__ float raw[CH_][TB_ * 6 + 8];     // 20 x 200
    __shared__ float2 xs6p[CH_][MM_][TB_];      // 20 x 6 x 32 float2 = 30KB

    int b = blockIdx.y;
    int T0 = blockIdx.x * TB_;
    int tid = threadIdx.y * TB_ + threadIdx.x;

    // Phase 1: coalesced load of x tile (198 floats per channel)
    for (int i = tid; i < CH_ * (TB_ * 6 + 6); i += 640) {
        int ci = i / (TB_ * 6 + 6);
        int j  = i % (TB_ * 6 + 6);
        int pos = 6 * T0 + j;
        raw[ci][j] = (pos < lin) ? x[((size_t)b * CH_ + ci) * lin + pos] : 0.f;
    }
    __syncthreads();

    // Phase 2: rearrange into paired-transposed layout
    for (int i = tid; i < CH_ * MM_ * TB_; i += 640) {
        int ci = i / (MM_ * TB_);
        int rem = i % (MM_ * TB_);
        int r = rem / TB_;
        int tau = rem % TB_;
        xs6p[ci][r][tau] = make_float2(raw[ci][6 * tau + r], raw[ci][6 * tau + r + 6]);
    }
    __syncthreads();

    int tau = threadIdx.x;
    int g = threadIdx.y;
    int t = T0 + tau;
    if (t >= ll) return;

    float v[MM_];
#pragma unroll
    for (int i = 0; i < MM_; i++) {
        int q  = 6 * g + i;
        int mi = q / CH_;
        int ci = q % CH_;
        float s = 0.f;
#pragma unroll
        for (int r = 0; r < MM_; r++) {
            float2 P = xs6p[ci][r][tau];
            s = fmaf(c_fd[mi * NPOLY + r],     P.x, s);
            s = fmaf(c_fd[mi * NPOLY + r + 6], P.y, s);
        }
        v[i] = s;
    }
#pragma unroll
    for (int o = 0; o < MM_; o++) {
        float s = 0.f;
#pragma unroll
        for (int i = 0; i < MM_; i++)
            s = fmaf(c_linm[lmofs + (g * MM_ + o) * MM_ + i], v[i], s);
        int p  = 6 * g + o;
        int mo = p / CH_;
        int co = p % CH_;
        Lg[(((size_t)b * MM_ + mo) * CH_ + co) * ll + t] = s;
    }
}

// ---------------------------------------------------------------------------
// Overlap-add reconstruction + residual + gelu, VT=6 (shared t0 per thread).
// Thread u handles outputs t=6u..6u+5 (all share t0=u+1, k0=t%6).
// Phase 1: coalesced Lg loads (lanes stride-1 in t0), 72 FMA, stage in smem.
// Phase 2: coalesced y2 load + gelu + coalesced store. Applies the 0.5.
// lout is always divisible by 6.
// ---------------------------------------------------------------------------
__global__ void __launch_bounds__(128) k_recon(
    const float* __restrict__ Lg, const float* __restrict__ y2,
    float* __restrict__ out, int ll, int lout)
{
    __shared__ float sbuf[128 * 6];

    int tid = threadIdx.x;
    int bc = blockIdx.y;
    int b = bc / CH_, co = bc % CH_;
    int nu = lout / 6;

    int u = blockIdx.x * 128 + tid;
    if (u < nu) {
        int t0 = u + 1;
        const float* Lo = Lg + (((size_t)b * MM_) * CH_ + co) * ll;
        size_t mstride = (size_t)CH_ * ll;
        float rec[6];
#pragma unroll
        for (int e = 0; e < 6; e++) rec[e] = 0.f;
#pragma unroll
        for (int m = 0; m < MM_; m++) {
            float uc = Lo[m * mstride + t0];
            float up = Lo[m * mstride + t0 - 1];
#pragma unroll
            for (int e = 0; e < 6; e++) {
                rec[e] = fmaf(uc, c_fr[m * NPOLY + e],     rec[e]);
                rec[e] = fmaf(up, c_fr[m * NPOLY + e + 6], rec[e]);
            }
        }
#pragma unroll
        for (int e = 0; e < 6; e++) sbuf[6 * tid + e] = rec[e];
    }
    __syncthreads();

    int Tbase = blockIdx.x * 768;
    int liny2 = lout + 8;
    const float* y2r = y2 + (size_t)bc * liny2;
    float* outr = out + (size_t)bc * lout;
#pragma unroll
    for (int e2 = 0; e2 < 6; e2++) {
        int idx = tid + 128 * e2;
        int t = Tbase + idx;
        if (t < lout)
            outr[t] = gelu_f(fmaf(0.5f, sbuf[idx], y2r[t + 4]));
    }
}

// ---------------------------------------------------------------------------
// Final 20->128(gelu)->1 with f32x2, VT=4.
// ---------------------------------------------------------------------------
__global__ void __launch_bounds__(128) k_final_f2(
    const float* __restrict__ x, const float* __restrict__ w11,
    const float* __restrict__ w_out, float* __restrict__ out, int lin)
{
    __shared__ __align__(16) float2 swd[128 * CH_];
    __shared__ float so[128];
    int tid = threadIdx.x;
    for (int i = tid; i < 128 * CH_; i += 128) {
        float v = w11[i];
        swd[i] = make_float2(v, v);
    }
    if (tid < 128) so[tid] = w_out[tid];
    __syncthreads();

    int b = blockIdx.y;
    int t0 = (blockIdx.x * 128 + tid) * 4;
    if (t0 >= LIN_) return;

    const float* xb = x + (size_t)b * CH_ * lin + t0;
    ull xv01[CH_], xv23[CH_];
#pragma unroll
    for (int c = 0; c < CH_; c++) {
        const float* xp = xb + c * lin;
        xv01[c] = pk2(xp[0], xp[1]);
        xv23[c] = pk2(xp[2], xp[3]);
    }

    ull zero = pk2(0.f, 0.f);
    ull acc01 = zero, acc23 = zero;
#pragma unroll 2
    for (int o = 0; o < 128; o++) {
        ull h01 = zero, h23 = zero;
#pragma unroll
        for (int c = 0; c < CH_; c++) {
            ull wv = *(const ull*)&swd[o * CH_ + c];
            h01 = fma2(wv, xv01[c], h01);
            h23 = fma2(wv, xv23[c], h23);
        }
        float h0, h1, h2, h3;
        upk2(h01, h0, h1); upk2(h23, h2, h3);
        float ov = so[o];
        ull ov2 = pk2(ov, ov);
        acc01 = fma2(ov2, pk2(gelu_f(h0), gelu_f(h1)), acc01);
        acc23 = fma2(ov2, pk2(gelu_f(h2), gelu_f(h3)), acc23);
    }
    float r0, r1, r2, r3;
    upk2(acc01, r0, r1); upk2(acc23, r2, r3);
    float4* op = (float4*)&out[(size_t)b * LIN_ + t0];
    *op = make_float4(r0, r1, r2, r3);
}

// ---------------------------------------------------------------------------
extern "C" void kernel_launch(void* const* d_in, const int* in_sizes, int n_in,
                              void* d_out, int out_size)
{
    const float* input  = (const float*)d_in[0];
    const float* w_first= (const float*)d_in[1];
    const float* conv_a = (const float*)d_in[2];
    const float* conv_b = (const float*)d_in[3];
    const float* lin_m  = (const float*)d_in[4];
    const float* w11    = (const float*)d_in[5];
    const float* w_out  = (const float*)d_in[6];
    const float* filt_d = (const float*)d_in[7];
    const float* filt_r = (const float*)d_in[8];
    float* out = (float*)d_out;

    // Upload weights to constant memory (D2D async, graph-capturable)
    cudaMemcpyToSymbolAsync(c_wfirst, w_first, 600 * 4, 0, cudaMemcpyDeviceToDevice, 0);
    cudaMemcpyToSymbolAsync(c_conva, conv_a, 4800 * 4, 0, cudaMemcpyDeviceToDevice, 0);
    cudaMemcpyToSymbolAsync(c_convb, conv_b, 4800 * 4, 0, cudaMemcpyDeviceToDevice, 0);
    cudaMemcpyToSymbolAsync(c_linm, lin_m, 2880 * 4, 0, cudaMemcpyDeviceToDevice, 0);
    cudaMemcpyToSymbolAsync(c_fd, filt_d, 72 * 4, 0, cudaMemcpyDeviceToDevice, 0);
    cudaMemcpyToSymbolAsync(c_fr, filt_r, 72 * 4, 0, cudaMemcpyDeviceToDevice, 0);

    float *xa, *xb, *y1, *y2;
    cudaGetSymbolAddress((void**)&xa, g_xa);
    cudaGetSymbolAddress((void**)&xb, g_xb);
    cudaGetSymbolAddress((void**)&y1, g_y1);
    cudaGetSymbolAddress((void**)&y2, g_y2);
    float* Lg = y1;  // y1 dead after conv_b (stream-ordered), legmix reuses it

    int l = 16434;
    {
        dim3 g((l + 127) / 128, B_);
        k_first<<<g, 128>>>(input, xa, l);
    }

    float* cur = xa;
    float* alt = xb;
    for (int i = 0; i < NB_; i++) {
        int l1 = l - 2;
        int l2 = l - 4;
        int ll = l / 6 - 1;
        int lo = l - 12;

        dim3 ga((l1 + NTC - 1) / NTC, B_);
        k_conv5c<true, true><<<ga, 128>>>(cur, y1, l, i * 1200);

        dim3 gb((l2 + NTC - 1) / NTC, B_);
        k_conv5c<false, false><<<gb, 128>>>(y1, y2, l1, i * 1200);

        dim3 gl((ll + TB_ - 1) / TB_, B_);
        k_legmix<<<gl, dim3(TB_, CH_)>>>(cur, Lg, l, ll, i * 720);

        dim3 gr((lo / 6 + 127) / 128, B_ * CH_);
        k_recon<<<gr, 128>>>(Lg, y2, alt, ll, lo);

        float* tmp = cur; cur = alt; alt = tmp;
        l = lo;
    }

    dim3 gf((LIN_ / 4 + 127) / 128, B_);
    k_final_f2<<<gf, 128>>>(cur, w11, w_out, out, l);
}

// round 7
// speedup vs baseline: 3.4003x; 3.4003x over previous
#include <cuda_runtime.h>
#include <math.h>

#define B_    32
#define INC_  10
#define LIN_  16384
#define CH_   20
#define NPOLY 12
#define MM_   6
#define NB_   4
// lengths: l0=16434 -> 16422,16410,16398,16386 (all divisible by 6)

#define BUFN 10520000  // >= 32*20*16434

__device__ float g_xa[BUFN];
__device__ float g_xb[BUFN];
__device__ float g_y1[BUFN];
__device__ float g_y2[BUFN];

typedef unsigned long long ull;

__device__ __forceinline__ ull pk2(float lo, float hi) {
    ull r; asm("mov.b64 %0, {%1, %2};" : "=l"(r) : "f"(lo), "f"(hi)); return r;
}
__device__ __forceinline__ void upk2(ull v, float& lo, float& hi) {
    asm("mov.b64 {%0, %1}, %2;" : "=f"(lo), "=f"(hi) : "l"(v));
}
__device__ __forceinline__ ull fma2(ull a, ull b, ull c) {
    ull d; asm("fma.rn.f32x2 %0, %1, %2, %3;" : "=l"(d) : "l"(a), "l"(b), "l"(c));
    return d;
}

// Branchless gelu: Abramowitz-Stegun 7.1.26 erf approx (|abs err| < 1.5e-7)
__device__ __forceinline__ float gelu_f(float x) {
    float z = 0.7071067811865476f * x;
    float s = fabsf(z);
    float t = __fdividef(1.0f, fmaf(0.3275911f, s, 1.0f));
    float p = fmaf(fmaf(fmaf(fmaf(1.061405429f, t, -1.453152027f),
                             t, 1.421413741f), t, -0.284496736f), t, 0.254829592f) * t;
    float e = __expf(-s * s);
    float er = fmaf(-p, e, 1.0f);
    er = copysignf(er, z);
    return 0.5f * x * (1.0f + er);
}

// ---------------------------------------------------------------------------
// First conv: input (B,10,16384) wrap-padded (25,27), conv3 -> (B,20,16434)
// (R2 version: smem weights)
// ---------------------------------------------------------------------------
__global__ void __launch_bounds__(128) k_first(
    const float* __restrict__ in, const float* __restrict__ w,
    float* __restrict__ out, int lout)
{
    __shared__ float sw[CH_ * INC_ * 3];
    int tid = threadIdx.x;
    for (int i = tid; i < CH_ * INC_ * 3; i += blockDim.x) sw[i] = w[i];
    __syncthreads();

    int b = blockIdx.y;
    int t = blockIdx.x * blockDim.x + tid;
    if (t >= lout) return;

    int base = t - 25;
    int i0 = base;     if (i0 < 0) i0 += LIN_; else if (i0 >= LIN_) i0 -= LIN_;
    int i1 = base + 1; if (i1 < 0) i1 += LIN_; else if (i1 >= LIN_) i1 -= LIN_;
    int i2 = base + 2; if (i2 < 0) i2 += LIN_; else if (i2 >= LIN_) i2 -= LIN_;

    const float* inb = in + (size_t)b * INC_ * LIN_;
    float acc[CH_];
#pragma unroll
    for (int co = 0; co < CH_; co++) acc[co] = 0.f;
#pragma unroll
    for (int ci = 0; ci < INC_; ci++) {
        float v0 = inb[ci * LIN_ + i0];
        float v1 = inb[ci * LIN_ + i1];
        float v2 = inb[ci * LIN_ + i2];
#pragma unroll
        for (int co = 0; co < CH_; co++) {
            const float* wp = sw + (co * INC_ + ci) * 3;
            acc[co] = fmaf(wp[0], v0, fmaf(wp[1], v1, fmaf(wp[2], v2, acc[co])));
        }
    }
    float* ob = out + (size_t)b * CH_ * lout;
#pragma unroll
    for (int co = 0; co < CH_; co++) ob[co * lout + t] = acc[co];
}

// ---------------------------------------------------------------------------
// conv3 20->20, VALID. 2 positions per thread (R2 version, exact).
// ---------------------------------------------------------------------------
template <bool DO_GELU>
__global__ void __launch_bounds__(128) k_conv20(
    const float* __restrict__ x, const float* __restrict__ w,
    float* __restrict__ out, int lin)
{
    __shared__ float sw[CH_ * CH_ * 3];
    int tid = threadIdx.x;
    for (int i = tid; i < CH_ * CH_ * 3; i += blockDim.x) sw[i] = w[i];
    __syncthreads();

    int lout = lin - 2;
    int b = blockIdx.y;
    int t0 = (blockIdx.x * blockDim.x + tid) * 2;
    if (t0 >= lout) return;
    bool has2 = (t0 + 1 < lout);

    const float* xb = x + (size_t)b * CH_ * lin;
    float a0[CH_], a1[CH_];
#pragma unroll
    for (int co = 0; co < CH_; co++) { a0[co] = 0.f; a1[co] = 0.f; }

#pragma unroll
    for (int ci = 0; ci < CH_; ci++) {
        const float* xp = xb + ci * lin + t0;
        float v0 = xp[0], v1 = xp[1], v2 = xp[2];
        float v3 = has2 ? xp[3] : 0.f;
#pragma unroll
        for (int co = 0; co < CH_; co++) {
            const float* wp = sw + (co * CH_ + ci) * 3;
            float w0 = wp[0], w1 = wp[1], w2 = wp[2];
            a0[co] = fmaf(w0, v0, fmaf(w1, v1, fmaf(w2, v2, a0[co])));
            a1[co] = fmaf(w0, v1, fmaf(w1, v2, fmaf(w2, v3, a1[co])));
        }
    }
    float* ob = out + (size_t)b * CH_ * lout;
#pragma unroll
    for (int co = 0; co < CH_; co++) {
        float u0 = a0[co], u1 = a1[co];
        if (DO_GELU) { u0 = gelu_f(u0); u1 = gelu_f(u1); }
        ob[co * lout + t0] = u0;
        if (has2) ob[co * lout + t0 + 1] = u1;
    }
}

// ---------------------------------------------------------------------------
// Legendre decomposition + cross-channel block-diag mixing (R2 version, exact).
// Flat mode-major axis: q = mi*20 + ci.
//   v[q,t] = sum_k (fd[mi,k]*0.5) * x[b, ci, 6t+k]
//   u[p,t] = sum_i lm[p/6, p%6, i] * v[6*(p/6)+i, t]
// Lg layout [b][mo][co][ll], p = mo*20+co.
// ---------------------------------------------------------------------------
#define TB_ 32
__global__ void __launch_bounds__(640) k_legmix(
    const float* __restrict__ x, const float* __restrict__ lm_g,
    const float* __restrict__ fd, float* __restrict__ Lg, int lin, int ll)
{
    __shared__ float xs[CH_][TB_ * 6 + 6];   // 20 x 198
    __shared__ float fd2[MM_ * NPOLY];
    __shared__ float lm[CH_ * MM_ * MM_];

    int b = blockIdx.y;
    int T0 = blockIdx.x * TB_;
    int tid = threadIdx.y * TB_ + threadIdx.x;

    for (int i = tid; i < MM_ * NPOLY; i += 640) fd2[i] = 0.5f * fd[i];
    for (int i = tid; i < CH_ * MM_ * MM_; i += 640) lm[i] = lm_g[i];
    for (int i = tid; i < CH_ * (TB_ * 6 + 6); i += 640) {
        int ci = i / (TB_ * 6 + 6);
        int j  = i % (TB_ * 6 + 6);
        int pos = 6 * T0 + j;
        xs[ci][j] = (pos < lin) ? x[((size_t)b * CH_ + ci) * lin + pos] : 0.f;
    }
    __syncthreads();

    int tloc = threadIdx.x;
    int g = threadIdx.y;
    int t = T0 + tloc;
    if (t >= ll) return;

    float v[MM_];
#pragma unroll
    for (int i = 0; i < MM_; i++) {
        int q  = 6 * g + i;
        int mi = q / CH_;
        int ci = q % CH_;
        float s = 0.f;
#pragma unroll
        for (int k = 0; k < NPOLY; k++)
            s = fmaf(fd2[mi * NPOLY + k], xs[ci][6 * tloc + k], s);
        v[i] = s;
    }
#pragma unroll
    for (int o = 0; o < MM_; o++) {
        float s = 0.f;
#pragma unroll
        for (int i = 0; i < MM_; i++)
            s = fmaf(lm[(g * MM_ + o) * MM_ + i], v[i], s);
        int p  = 6 * g + o;
        int mo = p / CH_;
        int co = p % CH_;
        Lg[(((size_t)b * MM_ + mo) * CH_ + co) * ll + t] = s;
    }
}

// ---------------------------------------------------------------------------
// Overlap-add reconstruction + residual + gelu, VT=6 (shared t0 per thread).
// Thread u: outputs t=6u..6u+5, all sharing t0=u+1, k0=e.
// Phase 1: 12 coalesced Lg loads + 72 FMA -> smem. Phase 2: coalesced
// y2 + gelu + coalesced store. fr staged via smem (NOT constant -> no LDC).
// NOTE: k_legmix already applied the 0.5, so no extra factor here.
// ---------------------------------------------------------------------------
__global__ void __launch_bounds__(128) k_recon(
    const float* __restrict__ Lg, const float* __restrict__ fr,
    const float* __restrict__ y2, float* __restrict__ out, int ll, int lout)
{
    __shared__ float sfr[MM_ * NPOLY];
    __shared__ float sbuf[128 * 6];

    int tid = threadIdx.x;
    if (tid < MM_ * NPOLY) sfr[tid] = fr[tid];
    __syncthreads();

    int bc = blockIdx.y;
    int b = bc / CH_, co = bc % CH_;
    int nu = lout / 6;

    int u = blockIdx.x * 128 + tid;
    if (u < nu) {
        int t0 = u + 1;
        const float* Lo = Lg + (((size_t)b * MM_) * CH_ + co) * ll;
        size_t mstride = (size_t)CH_ * ll;
        float rec[6];
#pragma unroll
        for (int e = 0; e < 6; e++) rec[e] = 0.f;
#pragma unroll
        for (int m = 0; m < MM_; m++) {
            float uc = Lo[m * mstride + t0];
            float up = Lo[m * mstride + t0 - 1];
#pragma unroll
            for (int e = 0; e < 6; e++) {
                rec[e] = fmaf(uc, sfr[m * NPOLY + e],     rec[e]);
                rec[e] = fmaf(up, sfr[m * NPOLY + e + 6], rec[e]);
            }
        }
#pragma unroll
        for (int e = 0; e < 6; e++) sbuf[6 * tid + e] = rec[e];
    }
    __syncthreads();

    int Tbase = blockIdx.x * 768;
    int liny2 = lout + 8;
    const float* y2r = y2 + (size_t)bc * liny2;
    float* outr = out + (size_t)bc * lout;
#pragma unroll
    for (int e2 = 0; e2 < 6; e2++) {
        int idx = tid + 128 * e2;
        int t = Tbase + idx;
        if (t < lout)
            outr[t] = gelu_f(sbuf[idx] + y2r[t + 4]);
    }
}

// ---------------------------------------------------------------------------
// Final 20->128(gelu)->1 with f32x2, VT=4 (R5 version, validated).
// ---------------------------------------------------------------------------
__global__ void __launch_bounds__(128) k_final_f2(
    const float* __restrict__ x, const float* __restrict__ w11,
    const float* __restrict__ w_out, float* __restrict__ out, int lin)
{
    __shared__ __align__(16) float2 swd[128 * CH_];
    __shared__ float so[128];
    int tid = threadIdx.x;
    for (int i = tid; i < 128 * CH_; i += 128) {
        float v = w11[i];
        swd[i] = make_float2(v, v);
    }
    if (tid < 128) so[tid] = w_out[tid];
    __syncthreads();

    int b = blockIdx.y;
    int t0 = (blockIdx.x * 128 + tid) * 4;
    if (t0 >= LIN_) return;

    const float* xb = x + (size_t)b * CH_ * lin + t0;
    ull xv01[CH_], xv23[CH_];
#pragma unroll
    for (int c = 0; c < CH_; c++) {
        const float* xp = xb + c * lin;
        xv01[c] = pk2(xp[0], xp[1]);
        xv23[c] = pk2(xp[2], xp[3]);
    }

    ull zero = pk2(0.f, 0.f);
    ull acc01 = zero, acc23 = zero;
#pragma unroll 2
    for (int o = 0; o < 128; o++) {
        ull h01 = zero, h23 = zero;
#pragma unroll
        for (int c = 0; c < CH_; c++) {
            ull wv = *(const ull*)&swd[o * CH_ + c];
            h01 = fma2(wv, xv01[c], h01);
            h23 = fma2(wv, xv23[c], h23);
        }
        float h0, h1, h2, h3;
        upk2(h01, h0, h1); upk2(h23, h2, h3);
        float ov = so[o];
        ull ov2 = pk2(ov, ov);
        acc01 = fma2(ov2, pk2(gelu_f(h0), gelu_f(h1)), acc01);
        acc23 = fma2(ov2, pk2(gelu_f(h2), gelu_f(h3)), acc23);
    }
    float r0, r1, r2, r3;
    upk2(acc01, r0, r1); upk2(acc23, r2, r3);
    float4* op = (float4*)&out[(size_t)b * LIN_ + t0];
    *op = make_float4(r0, r1, r2, r3);
}

// ---------------------------------------------------------------------------
extern "C" void kernel_launch(void* const* d_in, const int* in_sizes, int n_in,
                              void* d_out, int out_size)
{
    const float* input  = (const float*)d_in[0];
    const float* w_first= (const float*)d_in[1];
    const float* conv_a = (const float*)d_in[2];
    const float* conv_b = (const float*)d_in[3];
    const float* lin_m  = (const float*)d_in[4];
    const float* w11    = (const float*)d_in[5];
    const float* w_out  = (const float*)d_in[6];
    const float* filt_d = (const float*)d_in[7];
    const float* filt_r = (const float*)d_in[8];
    float* out = (float*)d_out;

    float *xa, *xb, *y1, *y2;
    cudaGetSymbolAddress((void**)&xa, g_xa);
    cudaGetSymbolAddress((void**)&xb, g_xb);
    cudaGetSymbolAddress((void**)&y1, g_y1);
    cudaGetSymbolAddress((void**)&y2, g_y2);
    float* Lg = y1;  // y1 dead after conv_b (stream-ordered); legmix reuses it

    int l = 16434;
    {
        dim3 g((l + 127) / 128, B_);
        k_first<<<g, 128>>>(input, w_first, xa, l);
    }

    float* cur = xa;
    float* alt = xb;
    for (int i = 0; i < NB_; i++) {
        int l1 = l - 2;
        int l2 = l - 4;
        int ll = l / 6 - 1;
        int lo = l - 12;

        dim3 ga((l1 + 255) / 256, B_);
        k_conv20<true><<<ga, 128>>>(cur, conv_a + i * CH_ * CH_ * 3, y1, l);

        dim3 gb((l2 + 255) / 256, B_);
        k_conv20<false><<<gb, 128>>>(y1, conv_b + i * CH_ * CH_ * 3, y2, l1);

        dim3 gl((ll + TB_ - 1) / TB_, B_);
        k_legmix<<<gl, dim3(TB_, CH_)>>>(cur, lin_m + i * CH_ * MM_ * MM_,
                                         filt_d, Lg, l, ll);

        dim3 gr((lo / 6 + 127) / 128, B_ * CH_);
        k_recon<<<gr, 128>>>(Lg, filt_r, y2, alt, ll, lo);

        float* tmp = cur; cur = alt; alt = tmp;
        l = lo;
    }

    dim3 gf((LIN_ / 4 + 127) / 128, B_);
    k_final_f2<<<gf, 128>>>(cur, w11, w_out, out, l);
}